// round 13
// baseline (speedup 1.0000x reference)
#include <cuda_runtime.h>
#include <cuda_fp16.h>
#include <math.h>
#include <cstdint>

// Problem constants
#define BB 4
#define SS 2048
#define DD 1024
#define HH 16
#define HD 64
#define MTOT (BB * SS)          // 8192
#define ELEMS (BB * SS * DD)    // 8,388,608
#define KDIM 1024

#define NSEG 64
#define SEGL (SS / NSEG)        // 32
#define NC (BB * DD)            // 4096

// ---------------------------------------------------------------------------
// Scratch (allocation-free: __device__ globals)
// ---------------------------------------------------------------------------
__device__ __half g_hx[ELEMS];         // x in fp16
__device__ __half g_ko[ELEMS];         // k projection (fp16)
__device__ __half g_ro[ELEMS];         // r projection (fp16)
__device__ __half g_vo[ELEMS];         // v projection (fp16)
__device__ __half g_y[ELEMS];          // gated y = sigmoid(r)*wkv (fp16)

// fp16 weights
__device__ __half g_hWr[DD * DD];
__device__ __half g_hWk[DD * DD];
__device__ __half g_hWv[DD * DD];
__device__ __half g_hWo[DD * DD];

// WKV scan scratch
__device__ float g_bs[NSEG * NC];
__device__ float g_bin[NSEG * NC];
__device__ float g_Cc[NSEG * NC];
__device__ float g_lP[NSEG * NC];
__device__ float g_ain[NSEG * NC];

// GroupNorm scratch: partial per (seg, b, head, half-warp)
__device__ float g_psum[NSEG * BB * HH * 2];
__device__ float g_psq[NSEG * BB * HH * 2];
__device__ float g_mean[BB * HH];
__device__ float g_rstd[BB * HH];

// ---------------------------------------------------------------------------
// helpers
// ---------------------------------------------------------------------------
__device__ __forceinline__ uint32_t smem_u32(const void* p) {
    uint32_t a;
    asm("{ .reg .u64 t; cvta.to.shared.u64 t, %1; cvt.u32.u64 %0, t; }"
        : "=r"(a) : "l"(p));
    return a;
}

__device__ __forceinline__ void cpa16(uint32_t s, const void* g) {
    asm volatile("cp.async.cg.shared.global [%0], [%1], 16;\n" :: "r"(s), "l"(g));
}
__device__ __forceinline__ void cpa_commit() {
    asm volatile("cp.async.commit_group;\n" ::: "memory");
}
template <int N>
__device__ __forceinline__ void cpa_wait() {
    asm volatile("cp.async.wait_group %0;\n" :: "n"(N) : "memory");
}

__device__ __forceinline__ void ldsm4(uint32_t* r, uint32_t addr) {
    asm volatile(
        "ldmatrix.sync.aligned.m8n8.x4.shared.b16 {%0,%1,%2,%3}, [%4];"
        : "=r"(r[0]), "=r"(r[1]), "=r"(r[2]), "=r"(r[3]) : "r"(addr));
}

__device__ __forceinline__ void mma_f16(float* c, const uint32_t* a,
                                        uint32_t b0, uint32_t b1) {
    asm volatile(
        "mma.sync.aligned.m16n8k16.row.col.f32.f16.f16.f32 "
        "{%0,%1,%2,%3}, {%4,%5,%6,%7}, {%8,%9}, {%0,%1,%2,%3};\n"
        : "+f"(c[0]), "+f"(c[1]), "+f"(c[2]), "+f"(c[3])
        : "r"(a[0]), "r"(a[1]), "r"(a[2]), "r"(a[3]), "r"(b0), "r"(b1));
}

__device__ __forceinline__ uint32_t pack_h2(float a, float b) {
    __half2 h = __float22half2_rn(make_float2(a, b));
    return *(uint32_t*)&h;
}

// ---------------------------------------------------------------------------
// Kernel: convert 4 weight matrices + x to fp16 (single launch)
// ---------------------------------------------------------------------------
__global__ void prep_all(const float* __restrict__ W0, const float* __restrict__ W1,
                         const float* __restrict__ W2, const float* __restrict__ W3,
                         const float* __restrict__ X,
                         __half* __restrict__ H0, __half* __restrict__ H1,
                         __half* __restrict__ H2, __half* __restrict__ H3,
                         __half* __restrict__ HX) {
    const int N4 = DD * DD / 4;      // per weight matrix
    const int X4 = ELEMS / 4;
    int idx = blockIdx.x * blockDim.x + threadIdx.x;
    const float* S;
    __half* D;
    int i;
    if (idx < 4 * N4) {
        int m = idx / N4;
        i = idx - m * N4;
        S = (m == 0) ? W0 : (m == 1) ? W1 : (m == 2) ? W2 : W3;
        D = (m == 0) ? H0 : (m == 1) ? H1 : (m == 2) ? H2 : H3;
    } else {
        i = idx - 4 * N4;
        if (i >= X4) return;
        S = X;
        D = HX;
    }
    float4 a = ((const float4*)S)[i];
    uint2 h;
    h.x = pack_h2(a.x, a.y);
    h.y = pack_h2(a.z, a.w);
    ((uint2*)D)[i] = h;
}

// ---------------------------------------------------------------------------
// Shared GEMM geometry + validated simple MMA body
// ---------------------------------------------------------------------------
#define WRB 80
#define PART_B (128 * WRB)
#define STAGE_B (2 * PART_B)
#define GSM_BYTES (3 * STAGE_B)

#define MMA_STAGE_BODY(baseA, baseB)                                          \
    do {                                                                      \
        _Pragma("unroll")                                                     \
        for (int ks = 0; ks < 2; ks++) {                                      \
            const uint32_t koff = (uint32_t)(ks * 32) + lhalf;                \
            uint32_t bf[2][4];                                                \
            _Pragma("unroll")                                                 \
            for (int np = 0; np < 2; np++) {                                  \
                uint32_t row = (uint32_t)(wn * 32 + np * 16) + lrow;          \
                ldsm4(bf[np], (baseB) + row * WRB + koff);                    \
            }                                                                 \
            _Pragma("unroll")                                                 \
            for (int mi = 0; mi < 4; mi++) {                                  \
                uint32_t arow = (uint32_t)(wm * 64 + mi * 16) + lrow;         \
                uint32_t ah[4];                                               \
                ldsm4(ah, (baseA) + arow * WRB + koff);                       \
                _Pragma("unroll")                                             \
                for (int ni = 0; ni < 4; ni++) {                              \
                    int np = ni >> 1, sel = ni & 1;                           \
                    mma_f16(c[mi][ni], ah, bf[np][sel], bf[np][sel + 2]);     \
                }                                                             \
            }                                                                 \
        }                                                                     \
    } while (0)

// ---------------------------------------------------------------------------
// r/k/v GEMM with fused token-shift mixing on the A operand:
//   A[m][c] = hx[m][c]*mix_z[c] + hx[m-1][c]*(1-mix_z[c])   (shift=0 at s==0)
// B (weights) via cp.async; A staged via ldg + fp32 mix + pack -> smem.
// blockIdx.z selects mix vector + weight + output.
// ---------------------------------------------------------------------------
__global__ __launch_bounds__(256, 2)
void gemm_rkv(const __half* __restrict__ HX,
              const float* __restrict__ M0, const __half* __restrict__ B0,
              __half* __restrict__ C0,
              const float* __restrict__ M1, const __half* __restrict__ B1,
              __half* __restrict__ C1,
              const float* __restrict__ M2, const __half* __restrict__ B2,
              __half* __restrict__ C2) {
    extern __shared__ char smc[];
    const uint32_t smb = smem_u32(smc);
    const int z = blockIdx.z;
    const float* Mx = (z == 0) ? M0 : (z == 1) ? M1 : M2;
    const __half* Bm = (z == 0) ? B0 : (z == 1) ? B1 : B2;
    __half* C = (z == 0) ? C0 : (z == 1) ? C1 : C2;

    const int tid = threadIdx.x;
    const int lane = tid & 31;
    const int wid = tid >> 5;
    const int wm = wid >> 2;
    const int wn = wid & 3;
    const int bm = blockIdx.y * 128;
    const int bn = blockIdx.x * 128;

    const __half* srcB = Bm + (size_t)bn * KDIM;

    const int arow0 = (tid + 0) >> 2, acc0 = (tid + 0) & 3;
    const int arow1 = (tid + 256) >> 2, acc1 = (tid + 256) & 3;

    float c[4][4][4];
#pragma unroll
    for (int i = 0; i < 4; i++)
#pragma unroll
        for (int j = 0; j < 4; j++)
#pragma unroll
            for (int q = 0; q < 4; q++) c[i][j][q] = 0.f;

    auto load_B = [&](int buf, int k0) {
#pragma unroll
        for (int i = 0; i < 2; i++) {
            int id = tid + i * 256;
            int row = id >> 2;
            int cc = id & 3;
            uint32_t saddr = smb + (uint32_t)(buf * STAGE_B + PART_B +
                                              row * WRB + cc * 16);
            cpa16(saddr, srcB + (size_t)row * KDIM + k0 + cc * 8);
        }
    };

    auto stage_A = [&](int buf, int k0) {
#pragma unroll
        for (int i = 0; i < 2; i++) {
            int row = (i == 0) ? arow0 : arow1;
            int cc = (i == 0) ? acc0 : acc1;
            int c0 = k0 + cc * 8;
            int m = bm + row;
            uint4 xr = *(const uint4*)(HX + (size_t)m * KDIM + c0);
            uint4 sr = make_uint4(0u, 0u, 0u, 0u);
            if ((m & (SS - 1)) != 0)
                sr = *(const uint4*)(HX + (size_t)(m - 1) * KDIM + c0);
            float4 m0 = *(const float4*)(Mx + c0);
            float4 m1 = *(const float4*)(Mx + c0 + 4);
            float2 x0 = __half22float2(*(__half2*)&xr.x);
            float2 x1 = __half22float2(*(__half2*)&xr.y);
            float2 x2 = __half22float2(*(__half2*)&xr.z);
            float2 x3 = __half22float2(*(__half2*)&xr.w);
            float2 s0 = __half22float2(*(__half2*)&sr.x);
            float2 s1 = __half22float2(*(__half2*)&sr.y);
            float2 s2 = __half22float2(*(__half2*)&sr.z);
            float2 s3 = __half22float2(*(__half2*)&sr.w);
            uint4 outv;
            outv.x = pack_h2(s0.x + (x0.x - s0.x) * m0.x,
                             s0.y + (x0.y - s0.y) * m0.y);
            outv.y = pack_h2(s1.x + (x1.x - s1.x) * m0.z,
                             s1.y + (x1.y - s1.y) * m0.w);
            outv.z = pack_h2(s2.x + (x2.x - s2.x) * m1.x,
                             s2.y + (x2.y - s2.y) * m1.y);
            outv.w = pack_h2(s3.x + (x3.x - s3.x) * m1.z,
                             s3.y + (x3.y - s3.y) * m1.w);
            *(uint4*)(smc + buf * STAGE_B + row * WRB + cc * 16) = outv;
        }
    };

    const uint32_t lrow = (uint32_t)(lane & 15);
    const uint32_t lhalf = (uint32_t)((lane >> 4) << 4);

    stage_A(0, 0);
    stage_A(1, 32);
    load_B(0, 0); cpa_commit();
    load_B(1, 32); cpa_commit();

#pragma unroll 1
    for (int it = 0; it < 32; ++it) {
        if (it < 31) cpa_wait<1>(); else cpa_wait<0>();
        __syncthreads();
        if (it + 2 < 32) {
            load_B((it + 2) % 3, (it + 2) * 32);
            cpa_commit();
            stage_A((it + 2) % 3, (it + 2) * 32);
        }

        const uint32_t baseA = smb + (uint32_t)((it % 3) * STAGE_B);
        const uint32_t baseB = baseA + PART_B;
        MMA_STAGE_BODY(baseA, baseB);
    }

#pragma unroll
    for (int mi = 0; mi < 4; mi++) {
        int r0 = bm + wm * 64 + mi * 16 + (lane >> 2);
#pragma unroll
        for (int ni = 0; ni < 4; ni++) {
            int col = bn + wn * 32 + ni * 8 + 2 * (lane & 3);
            __half2 h01 = __float22half2_rn(make_float2(c[mi][ni][0], c[mi][ni][1]));
            __half2 h23 = __float22half2_rn(make_float2(c[mi][ni][2], c[mi][ni][3]));
            *(__half2*)(C + (size_t)r0 * DD + col) = h01;
            *(__half2*)(C + (size_t)(r0 + 8) * DD + col) = h23;
        }
    }
}

// ---------------------------------------------------------------------------
// Wo GEMM with fused GroupNorm on the A operand (validated round 11)
// ---------------------------------------------------------------------------
__global__ __launch_bounds__(256, 2)
void gemm_wo(const __half* __restrict__ Y, const __half* __restrict__ Bw,
             float* __restrict__ C,
             const float* __restrict__ gamma, const float* __restrict__ beta) {
    extern __shared__ char smc[];
    const uint32_t smb = smem_u32(smc);

    const int tid = threadIdx.x;
    const int lane = tid & 31;
    const int wid = tid >> 5;
    const int wm = wid >> 2;
    const int wn = wid & 3;
    const int bm = blockIdx.y * 128;
    const int bn = blockIdx.x * 128;

    const __half* srcB = Bw + (size_t)bn * KDIM;

    const int arow0 = (tid + 0) >> 2, acc0 = (tid + 0) & 3;
    const int arow1 = (tid + 256) >> 2, acc1 = (tid + 256) & 3;

    float c[4][4][4];
#pragma unroll
    for (int i = 0; i < 4; i++)
#pragma unroll
        for (int j = 0; j < 4; j++)
#pragma unroll
            for (int q = 0; q < 4; q++) c[i][j][q] = 0.f;

    auto load_B = [&](int buf, int k0) {
#pragma unroll
        for (int i = 0; i < 2; i++) {
            int id = tid + i * 256;
            int row = id >> 2;
            int cc = id & 3;
            uint32_t saddr = smb + (uint32_t)(buf * STAGE_B + PART_B +
                                              row * WRB + cc * 16);
            cpa16(saddr, srcB + (size_t)row * KDIM + k0 + cc * 8);
        }
    };

    auto stage_A = [&](int buf, int k0) {
#pragma unroll
        for (int i = 0; i < 2; i++) {
            int row = (i == 0) ? arow0 : arow1;
            int cc = (i == 0) ? acc0 : acc1;
            int c0 = k0 + cc * 8;
            int m = bm + row;
            uint4 raw = *(const uint4*)(Y + (size_t)m * KDIM + c0);
            int grp = (m >> 11) * HH + (c0 >> 6);
            float mean = __ldg(g_mean + grp);
            float rstd = __ldg(g_rstd + grp);
            float4 ga0 = *(const float4*)(gamma + c0);
            float4 ga1 = *(const float4*)(gamma + c0 + 4);
            float4 be0 = *(const float4*)(beta + c0);
            float4 be1 = *(const float4*)(beta + c0 + 4);
            float2 y0 = __half22float2(*(__half2*)&raw.x);
            float2 y1 = __half22float2(*(__half2*)&raw.y);
            float2 y2 = __half22float2(*(__half2*)&raw.z);
            float2 y3 = __half22float2(*(__half2*)&raw.w);
            uint4 outv;
            outv.x = pack_h2((y0.x - mean) * rstd * ga0.x + be0.x,
                             (y0.y - mean) * rstd * ga0.y + be0.y);
            outv.y = pack_h2((y1.x - mean) * rstd * ga0.z + be0.z,
                             (y1.y - mean) * rstd * ga0.w + be0.w);
            outv.z = pack_h2((y2.x - mean) * rstd * ga1.x + be1.x,
                             (y2.y - mean) * rstd * ga1.y + be1.y);
            outv.w = pack_h2((y3.x - mean) * rstd * ga1.z + be1.z,
                             (y3.y - mean) * rstd * ga1.w + be1.w);
            *(uint4*)(smc + buf * STAGE_B + row * WRB + cc * 16) = outv;
        }
    };

    const uint32_t lrow = (uint32_t)(lane & 15);
    const uint32_t lhalf = (uint32_t)((lane >> 4) << 4);

    stage_A(0, 0);
    stage_A(1, 32);
    load_B(0, 0); cpa_commit();
    load_B(1, 32); cpa_commit();

#pragma unroll 1
    for (int it = 0; it < 32; ++it) {
        if (it < 31) cpa_wait<1>(); else cpa_wait<0>();
        __syncthreads();
        if (it + 2 < 32) {
            load_B((it + 2) % 3, (it + 2) * 32);
            cpa_commit();
            stage_A((it + 2) % 3, (it + 2) * 32);
        }

        const uint32_t baseA = smb + (uint32_t)((it % 3) * STAGE_B);
        const uint32_t baseB = baseA + PART_B;
        MMA_STAGE_BODY(baseA, baseB);
    }

#pragma unroll
    for (int mi = 0; mi < 4; mi++) {
        int r0 = bm + wm * 64 + mi * 16 + (lane >> 2);
#pragma unroll
        for (int ni = 0; ni < 4; ni++) {
            int col = bn + wn * 32 + ni * 8 + 2 * (lane & 3);
            float2 v01 = make_float2(c[mi][ni][0], c[mi][ni][1]);
            float2 v23 = make_float2(c[mi][ni][2], c[mi][ni][3]);
            *(float2*)(C + (size_t)r0 * DD + col) = v01;
            *(float2*)(C + (size_t)(r0 + 8) * DD + col) = v23;
        }
    }
}

// ---------------------------------------------------------------------------
// WKV segmented scan — exact reference recurrence with exp(0)-elimination
// ---------------------------------------------------------------------------
__global__ void wkv_p1(const float* __restrict__ td) {
    int gid = blockIdx.x * blockDim.x + threadIdx.x;
    if (gid >= NSEG * NC) return;
    int c = gid % DD;
    int r = gid / DD;
    int b = r % BB;
    int seg = r / BB;
    float w = -__expf(td[c]);
    const __half* kp = g_ko + ((size_t)b * SS + (size_t)seg * SEGL) * DD + c;
    float bb = -1e38f;
#pragma unroll 4
    for (int t = 0; t < SEGL; t++) {
        float kt = __half2float(kp[(size_t)t * DD]);
        float ww = bb + w;
        float d = ww - kt;
        float em = __expf(-fabsf(d));
        float p2 = fmaxf(ww, kt);
        bb = p2 + __logf(1.f + em + 1e-8f);
    }
    g_bs[seg * NC + b * DD + c] = bb;
}

__global__ void wkv_p2(const float* __restrict__ td) {
    int ch = blockIdx.x * blockDim.x + threadIdx.x;
    if (ch >= NC) return;
    int c = ch % DD;
    float w = -__expf(td[c]);
    float Lw = (float)SEGL * w;
    float bin = -1e38f;
#pragma unroll
    for (int s = 0; s < NSEG; s++) {
        g_bin[s * NC + ch] = bin;
        float x = bin + Lw;
        float y = g_bs[s * NC + ch];
        float em = __expf(-fabsf(x - y));
        bin = fmaxf(x, y) + __logf(1.f + em);
    }
}

__global__ void wkv_p3(const float* __restrict__ td) {
    int gid = blockIdx.x * blockDim.x + threadIdx.x;
    if (gid >= NSEG * NC) return;
    int c = gid % DD;
    int r = gid / DD;
    int b = r % BB;
    int seg = r / BB;
    float w = -__expf(td[c]);
    const __half* kp = g_ko + ((size_t)b * SS + (size_t)seg * SEGL) * DD + c;
    const __half* vp = g_vo + ((size_t)b * SS + (size_t)seg * SEGL) * DD + c;
    int sidx = seg * NC + b * DD + c;
    float bb = g_bin[sidx];
    float aa = 0.f, lP = 0.f;
#pragma unroll 4
    for (int t = 0; t < SEGL; t++) {
        float kt = __half2float(kp[(size_t)t * DD]);
        float vt = __half2float(vp[(size_t)t * DD]);
        float ww = bb + w;
        float d = ww - kt;
        lP += fminf(d, 0.f);
        float em = __expf(-fabsf(d));
        float e1b = (d >= 0.f) ? 1.f : em;
        float e2b = (d >= 0.f) ? em : 1.f;
        aa = e1b * aa + e2b * vt;
        bb = fmaxf(ww, kt) + __logf(1.f + em + 1e-8f);
    }
    g_Cc[sidx] = aa;
    g_lP[sidx] = lP;
}

__global__ void wkv_p4() {
    int ch = blockIdx.x * blockDim.x + threadIdx.x;
    if (ch >= NC) return;
    float ain = 0.f;
#pragma unroll
    for (int s = 0; s < NSEG; s++) {
        g_ain[s * NC + ch] = ain;
        ain = __expf(g_lP[s * NC + ch]) * ain + g_Cc[s * NC + ch];
    }
}

// Replay + sigmoid gate + fp16 y + GroupNorm partials (warp-shuffle)
__global__ void wkv_p5(const float* __restrict__ td, const float* __restrict__ tf) {
    int gid = blockIdx.x * blockDim.x + threadIdx.x;
    if (gid >= NSEG * NC) return;
    int c = gid % DD;
    int r = gid / DD;
    int b = r % BB;
    int seg = r / BB;
    float w = -__expf(td[c]);
    float u = tf[c];
    size_t off0 = ((size_t)b * SS + (size_t)seg * SEGL) * DD + c;
    const __half* kp = g_ko + off0;
    const __half* vp = g_vo + off0;
    const __half* rp = g_ro + off0;
    __half* yp = g_y + off0;
    int sidx = seg * NC + b * DD + c;
    float aa = g_ain[sidx];
    float bb = g_bin[sidx];
    float sum = 0.f, sq = 0.f;
#pragma unroll 2
    for (int t = 0; t < SEGL; t++) {
        float kt = __half2float(kp[(size_t)t * DD]);
        float vt = __half2float(vp[(size_t)t * DD]);
        float rv = __half2float(rp[(size_t)t * DD]);

        float wk = kt + u;
        float d1 = bb - wk;
        float em1 = __expf(-fabsf(d1));
        float e1 = (d1 >= 0.f) ? 1.f : em1;
        float e2 = (d1 >= 0.f) ? em1 : 1.f;
        float num = e1 * aa + e2 * vt;
        float den = 1.f + em1 + 1e-8f;
        float sg = 1.f + __expf(-rv);
        float y = num * __fdividef(1.f, den * sg);
        yp[(size_t)t * DD] = __float2half_rn(y);
        sum += y;
        sq += y * y;

        float ww = bb + w;
        float d = ww - kt;
        float em = __expf(-fabsf(d));
        float e1b = (d >= 0.f) ? 1.f : em;
        float e2b = (d >= 0.f) ? em : 1.f;
        aa = e1b * aa + e2b * vt;
        bb = fmaxf(ww, kt) + __logf(1.f + em + 1e-8f);
    }

#pragma unroll
    for (int o = 16; o > 0; o >>= 1) {
        sum += __shfl_down_sync(0xFFFFFFFFu, sum, o);
        sq += __shfl_down_sync(0xFFFFFFFFu, sq, o);
    }
    if ((threadIdx.x & 31) == 0) {
        int h = c >> 6;
        int half = (c >> 5) & 1;
        int pidx = (((seg * BB + b) * HH) + h) * 2 + half;
        g_psum[pidx] = sum;
        g_psq[pidx] = sq;
    }
}

// ---------------------------------------------------------------------------
// GroupNorm stats
// ---------------------------------------------------------------------------
__global__ void gn_mid() {
    int g = threadIdx.x;
    if (g >= BB * HH) return;
    int b = g / HH, h = g % HH;
    float s = 0.f, q = 0.f;
#pragma unroll
    for (int seg = 0; seg < NSEG; seg++) {
        int base = (((seg * BB + b) * HH) + h) * 2;
        s += g_psum[base] + g_psum[base + 1];
        q += g_psq[base] + g_psq[base + 1];
    }
    const float inv = 1.f / (float)(SS * HD);
    float mean = s * inv;
    float var = q * inv - mean * mean;
    g_mean[g] = mean;
    g_rstd[g] = rsqrtf(var + 1e-5f);
}

// ---------------------------------------------------------------------------
// Launch
// ---------------------------------------------------------------------------
extern "C" void kernel_launch(void* const* d_in, const int* in_sizes, int n_in,
                              void* d_out, int out_size) {
    const float* x     = (const float*)d_in[0];
    const float* tmr   = (const float*)d_in[1];
    const float* tmk   = (const float*)d_in[2];
    const float* tmv   = (const float*)d_in[3];
    const float* Wr    = (const float*)d_in[4];
    const float* Wk    = (const float*)d_in[5];
    const float* Wv    = (const float*)d_in[6];
    const float* Wo    = (const float*)d_in[7];
    const float* td    = (const float*)d_in[8];
    const float* tf    = (const float*)d_in[9];
    const float* gamma = (const float*)d_in[10];
    const float* beta  = (const float*)d_in[11];
    float* out = (float*)d_out;

    __half *hx, *ko, *ro, *vo, *yv, *hwr, *hwk, *hwv, *hwo;
    cudaGetSymbolAddress((void**)&hx, g_hx);
    cudaGetSymbolAddress((void**)&ko, g_ko);
    cudaGetSymbolAddress((void**)&ro, g_ro);
    cudaGetSymbolAddress((void**)&vo, g_vo);
    cudaGetSymbolAddress((void**)&yv, g_y);
    cudaGetSymbolAddress((void**)&hwr, g_hWr);
    cudaGetSymbolAddress((void**)&hwk, g_hWk);
    cudaGetSymbolAddress((void**)&hwv, g_hWv);
    cudaGetSymbolAddress((void**)&hwo, g_hWo);

    cudaFuncSetAttribute(gemm_rkv,
                         cudaFuncAttributeMaxDynamicSharedMemorySize, GSM_BYTES);
    cudaFuncSetAttribute(gemm_wo,
                         cudaFuncAttributeMaxDynamicSharedMemorySize, GSM_BYTES);

    // 1. weights + x -> fp16 (one launch)
    const int PTOT = 4 * (DD * DD / 4) + ELEMS / 4;
    prep_all<<<(PTOT + 255) / 256, 256>>>(Wr, Wk, Wv, Wo, x,
                                          hwr, hwk, hwv, hwo, hx);

    // 2. r/k/v projections with fused token-shift mixing -> fp16
    dim3 gg3(DD / 128, MTOT / 128, 3);
    gemm_rkv<<<gg3, 256, GSM_BYTES>>>(hx,
                                      tmr, hwr, ro,
                                      tmk, hwk, ko,
                                      tmv, hwv, vo);

    // 3. segmented WKV scan (NSEG=64) + gate + GN partials in p5
    wkv_p1<<<(NSEG * NC + 255) / 256, 256>>>(td);
    wkv_p2<<<(NC + 255) / 256, 256>>>(td);
    wkv_p3<<<(NSEG * NC + 255) / 256, 256>>>(td);
    wkv_p4<<<(NC + 255) / 256, 256>>>();
    wkv_p5<<<(NSEG * NC + 255) / 256, 256>>>(td, tf);

    // 4. GroupNorm stats
    gn_mid<<<1, 64>>>();

    // 5. output projection with fused GroupNorm on A
    dim3 gg1(DD / 128, MTOT / 128);
    gemm_wo<<<gg1, 256, GSM_BYTES>>>(yv, hwo, out, gamma, beta);
}

// round 14
// speedup vs baseline: 1.1090x; 1.1090x over previous
#include <cuda_runtime.h>
#include <cuda_fp16.h>
#include <math.h>
#include <cstdint>

// Problem constants
#define BB 4
#define SS 2048
#define DD 1024
#define HH 16
#define HD 64
#define MTOT (BB * SS)          // 8192
#define ELEMS (BB * SS * DD)    // 8,388,608
#define KDIM 1024

#define NSEG 64
#define SEGL (SS / NSEG)        // 32
#define NC (BB * DD)            // 4096

// ---------------------------------------------------------------------------
// Scratch (allocation-free: __device__ globals)
// ---------------------------------------------------------------------------
__device__ __half g_ko[ELEMS];         // k projection (fp16)
__device__ __half g_ro[ELEMS];         // r projection (fp16)
__device__ __half g_vo[ELEMS];         // v projection (fp16)
__device__ __half g_y[ELEMS];          // gated y = sigmoid(r)*wkv (fp16)

// fp16 activations (mix outputs)
__device__ __half g_hxr[ELEMS];
__device__ __half g_hxk[ELEMS];
__device__ __half g_hxv[ELEMS];

// fp16 weights
__device__ __half g_hWr[DD * DD];
__device__ __half g_hWk[DD * DD];
__device__ __half g_hWv[DD * DD];
__device__ __half g_hWo[DD * DD];

// WKV scan scratch
__device__ float g_bs[NSEG * NC];
__device__ float g_bin[NSEG * NC];
__device__ float g_Cc[NSEG * NC];
__device__ float g_lP[NSEG * NC];
__device__ float g_ain[NSEG * NC];

// GroupNorm scratch: partial per (seg, b, head, half-warp)
__device__ float g_psum[NSEG * BB * HH * 2];
__device__ float g_psq[NSEG * BB * HH * 2];
__device__ float g_mean[BB * HH];
__device__ float g_rstd[BB * HH];

// ---------------------------------------------------------------------------
// helpers
// ---------------------------------------------------------------------------
__device__ __forceinline__ uint32_t smem_u32(const void* p) {
    uint32_t a;
    asm("{ .reg .u64 t; cvta.to.shared.u64 t, %1; cvt.u32.u64 %0, t; }"
        : "=r"(a) : "l"(p));
    return a;
}

__device__ __forceinline__ void cpa16(uint32_t s, const void* g) {
    asm volatile("cp.async.cg.shared.global [%0], [%1], 16;\n" :: "r"(s), "l"(g));
}
__device__ __forceinline__ void cpa_commit() {
    asm volatile("cp.async.commit_group;\n" ::: "memory");
}
template <int N>
__device__ __forceinline__ void cpa_wait() {
    asm volatile("cp.async.wait_group %0;\n" :: "n"(N) : "memory");
}

__device__ __forceinline__ void ldsm4(uint32_t* r, uint32_t addr) {
    asm volatile(
        "ldmatrix.sync.aligned.m8n8.x4.shared.b16 {%0,%1,%2,%3}, [%4];"
        : "=r"(r[0]), "=r"(r[1]), "=r"(r[2]), "=r"(r[3]) : "r"(addr));
}

__device__ __forceinline__ void mma_f16(float* c, const uint32_t* a,
                                        uint32_t b0, uint32_t b1) {
    asm volatile(
        "mma.sync.aligned.m16n8k16.row.col.f32.f16.f16.f32 "
        "{%0,%1,%2,%3}, {%4,%5,%6,%7}, {%8,%9}, {%0,%1,%2,%3};\n"
        : "+f"(c[0]), "+f"(c[1]), "+f"(c[2]), "+f"(c[3])
        : "r"(a[0]), "r"(a[1]), "r"(a[2]), "r"(a[3]), "r"(b0), "r"(b1));
}

__device__ __forceinline__ uint32_t pack_h2(float a, float b) {
    __half2 h = __float22half2_rn(make_float2(a, b));
    return *(uint32_t*)&h;
}

// ---------------------------------------------------------------------------
// Kernel: convert 4 weight matrices fp32 -> fp16 (single launch)
// ---------------------------------------------------------------------------
__global__ void prep_w4(const float* __restrict__ W0, const float* __restrict__ W1,
                        const float* __restrict__ W2, const float* __restrict__ W3,
                        __half* __restrict__ H0, __half* __restrict__ H1,
                        __half* __restrict__ H2, __half* __restrict__ H3) {
    const int N4 = DD * DD / 4;
    int idx = blockIdx.x * blockDim.x + threadIdx.x;
    if (idx >= 4 * N4) return;
    int m = idx / N4;
    int i = idx - m * N4;
    const float* W = (m == 0) ? W0 : (m == 1) ? W1 : (m == 2) ? W2 : W3;
    __half* H = (m == 0) ? H0 : (m == 1) ? H1 : (m == 2) ? H2 : H3;
    float4 a = ((const float4*)W)[i];
    uint2 h;
    h.x = pack_h2(a.x, a.y);
    h.y = pack_h2(a.z, a.w);
    ((uint2*)H)[i] = h;
}

// ---------------------------------------------------------------------------
// Kernel: token shift + mixing -> fp16 xr, xk, xv
// ---------------------------------------------------------------------------
__global__ void mix_kernel(const float* __restrict__ x,
                           const float* __restrict__ tmr,
                           const float* __restrict__ tmk,
                           const float* __restrict__ tmv) {
    int idx = blockIdx.x * blockDim.x + threadIdx.x;
    const int TOT4 = ELEMS / 4;
    if (idx >= TOT4) return;
    const int D4 = DD / 4;
    int d4 = idx % D4;
    int bs = idx / D4;
    int s = bs % SS;

    const float4* x4 = (const float4*)x;
    float4 xv_ = x4[idx];
    float4 sh = (s > 0) ? x4[idx - D4] : make_float4(0.f, 0.f, 0.f, 0.f);
    float4 mr = ((const float4*)tmr)[d4];
    float4 mk = ((const float4*)tmk)[d4];
    float4 mv = ((const float4*)tmv)[d4];

    uint2 h;
    h.x = pack_h2(xv_.x * mr.x + sh.x * (1.f - mr.x),
                  xv_.y * mr.y + sh.y * (1.f - mr.y));
    h.y = pack_h2(xv_.z * mr.z + sh.z * (1.f - mr.z),
                  xv_.w * mr.w + sh.w * (1.f - mr.w));
    ((uint2*)g_hxr)[idx] = h;
    h.x = pack_h2(xv_.x * mk.x + sh.x * (1.f - mk.x),
                  xv_.y * mk.y + sh.y * (1.f - mk.y));
    h.y = pack_h2(xv_.z * mk.z + sh.z * (1.f - mk.z),
                  xv_.w * mk.w + sh.w * (1.f - mk.w));
    ((uint2*)g_hxk)[idx] = h;
    h.x = pack_h2(xv_.x * mv.x + sh.x * (1.f - mv.x),
                  xv_.y * mv.y + sh.y * (1.f - mv.y));
    h.y = pack_h2(xv_.z * mv.z + sh.z * (1.f - mv.z),
                  xv_.w * mv.w + sh.w * (1.f - mv.w));
    ((uint2*)g_hxv)[idx] = h;
}

// ---------------------------------------------------------------------------
// Shared GEMM geometry + validated simple MMA body
// ---------------------------------------------------------------------------
#define WRB 80
#define PART_B (128 * WRB)
#define STAGE_B (2 * PART_B)
#define GSM_BYTES (3 * STAGE_B)

#define MMA_STAGE_BODY(baseA, baseB)                                          \
    do {                                                                      \
        _Pragma("unroll")                                                     \
        for (int ks = 0; ks < 2; ks++) {                                      \
            const uint32_t koff = (uint32_t)(ks * 32) + lhalf;                \
            uint32_t bf[2][4];                                                \
            _Pragma("unroll")                                                 \
            for (int np = 0; np < 2; np++) {                                  \
                uint32_t row = (uint32_t)(wn * 32 + np * 16) + lrow;          \
                ldsm4(bf[np], (baseB) + row * WRB + koff);                    \
            }                                                                 \
            _Pragma("unroll")                                                 \
            for (int mi = 0; mi < 4; mi++) {                                  \
                uint32_t arow = (uint32_t)(wm * 64 + mi * 16) + lrow;         \
                uint32_t ah[4];                                               \
                ldsm4(ah, (baseA) + arow * WRB + koff);                       \
                _Pragma("unroll")                                             \
                for (int ni = 0; ni < 4; ni++) {                              \
                    int np = ni >> 1, sel = ni & 1;                           \
                    mma_f16(c[mi][ni], ah, bf[np][sel], bf[np][sel + 2]);     \
                }                                                             \
            }                                                                 \
        }                                                                     \
    } while (0)

// ---------------------------------------------------------------------------
// r/k/v GEMM: fp16 in, fp16 out (all three) — round-12 validated version
// ---------------------------------------------------------------------------
__global__ __launch_bounds__(256, 2)
void gemm_rkv(const __half* __restrict__ A0, const __half* __restrict__ B0,
              __half* __restrict__ C0,
              const __half* __restrict__ A1, const __half* __restrict__ B1,
              __half* __restrict__ C1,
              const __half* __restrict__ A2, const __half* __restrict__ B2,
              __half* __restrict__ C2) {
    extern __shared__ char smc[];
    const uint32_t smb = smem_u32(smc);
    const int z = blockIdx.z;
    const __half* A = (z == 0) ? A0 : (z == 1) ? A1 : A2;
    const __half* Bm = (z == 0) ? B0 : (z == 1) ? B1 : B2;
    __half* C = (z == 0) ? C0 : (z == 1) ? C1 : C2;

    const int tid = threadIdx.x;
    const int lane = tid & 31;
    const int wid = tid >> 5;
    const int wm = wid >> 2;
    const int wn = wid & 3;
    const int bm = blockIdx.y * 128;
    const int bn = blockIdx.x * 128;

    const __half* srcA = A + (size_t)bm * KDIM;
    const __half* srcB = Bm + (size_t)bn * KDIM;

    float c[4][4][4];
#pragma unroll
    for (int i = 0; i < 4; i++)
#pragma unroll
        for (int j = 0; j < 4; j++)
#pragma unroll
            for (int q = 0; q < 4; q++) c[i][j][q] = 0.f;

    auto load_stage = [&](int buf, int k0) {
#pragma unroll
        for (int i = 0; i < 4; i++) {
            int id = tid + i * 256;
            int part = id >> 9;
            int pid = id & 511;
            int row = pid >> 2;
            int cc = pid & 3;
            uint32_t saddr = smb + (uint32_t)(buf * STAGE_B + part * PART_B +
                                              row * WRB + cc * 16);
            const __half* g = (part == 0 ? srcA : srcB) + (size_t)row * KDIM +
                              k0 + cc * 8;
            cpa16(saddr, g);
        }
    };

    const uint32_t lrow = (uint32_t)(lane & 15);
    const uint32_t lhalf = (uint32_t)((lane >> 4) << 4);

    load_stage(0, 0); cpa_commit();
    load_stage(1, 32); cpa_commit();

#pragma unroll 1
    for (int it = 0; it < 32; ++it) {
        if (it < 31) cpa_wait<1>(); else cpa_wait<0>();
        __syncthreads();
        if (it + 2 < 32) {
            load_stage((it + 2) % 3, (it + 2) * 32);
            cpa_commit();
        }

        const uint32_t baseA = smb + (uint32_t)((it % 3) * STAGE_B);
        const uint32_t baseB = baseA + PART_B;
        MMA_STAGE_BODY(baseA, baseB);
    }

#pragma unroll
    for (int mi = 0; mi < 4; mi++) {
        int r0 = bm + wm * 64 + mi * 16 + (lane >> 2);
#pragma unroll
        for (int ni = 0; ni < 4; ni++) {
            int col = bn + wn * 32 + ni * 8 + 2 * (lane & 3);
            __half2 h01 = __float22half2_rn(make_float2(c[mi][ni][0], c[mi][ni][1]));
            __half2 h23 = __float22half2_rn(make_float2(c[mi][ni][2], c[mi][ni][3]));
            *(__half2*)(C + (size_t)r0 * DD + col) = h01;
            *(__half2*)(C + (size_t)(r0 + 8) * DD + col) = h23;
        }
    }
}

// ---------------------------------------------------------------------------
// Wo GEMM with fused GroupNorm on the A operand (validated round 11/12)
// ---------------------------------------------------------------------------
__global__ __launch_bounds__(256, 2)
void gemm_wo(const __half* __restrict__ Y, const __half* __restrict__ Bw,
             float* __restrict__ C,
             const float* __restrict__ gamma, const float* __restrict__ beta) {
    extern __shared__ char smc[];
    const uint32_t smb = smem_u32(smc);

    const int tid = threadIdx.x;
    const int lane = tid & 31;
    const int wid = tid >> 5;
    const int wm = wid >> 2;
    const int wn = wid & 3;
    const int bm = blockIdx.y * 128;
    const int bn = blockIdx.x * 128;

    const __half* srcB = Bw + (size_t)bn * KDIM;

    const int arow0 = (tid + 0) >> 2, acc0 = (tid + 0) & 3;
    const int arow1 = (tid + 256) >> 2, acc1 = (tid + 256) & 3;

    float c[4][4][4];
#pragma unroll
    for (int i = 0; i < 4; i++)
#pragma unroll
        for (int j = 0; j < 4; j++)
#pragma unroll
            for (int q = 0; q < 4; q++) c[i][j][q] = 0.f;

    auto load_B = [&](int buf, int k0) {
#pragma unroll
        for (int i = 0; i < 2; i++) {
            int id = tid + i * 256;
            int row = id >> 2;
            int cc = id & 3;
            uint32_t saddr = smb + (uint32_t)(buf * STAGE_B + PART_B +
                                              row * WRB + cc * 16);
            cpa16(saddr, srcB + (size_t)row * KDIM + k0 + cc * 8);
        }
    };

    auto stage_A = [&](int buf, int k0) {
#pragma unroll
        for (int i = 0; i < 2; i++) {
            int row = (i == 0) ? arow0 : arow1;
            int cc = (i == 0) ? acc0 : acc1;
            int c0 = k0 + cc * 8;
            int m = bm + row;
            uint4 raw = *(const uint4*)(Y + (size_t)m * KDIM + c0);
            int grp = (m >> 11) * HH + (c0 >> 6);
            float mean = __ldg(g_mean + grp);
            float rstd = __ldg(g_rstd + grp);
            float4 ga0 = *(const float4*)(gamma + c0);
            float4 ga1 = *(const float4*)(gamma + c0 + 4);
            float4 be0 = *(const float4*)(beta + c0);
            float4 be1 = *(const float4*)(beta + c0 + 4);
            float2 y0 = __half22float2(*(__half2*)&raw.x);
            float2 y1 = __half22float2(*(__half2*)&raw.y);
            float2 y2 = __half22float2(*(__half2*)&raw.z);
            float2 y3 = __half22float2(*(__half2*)&raw.w);
            uint4 outv;
            outv.x = pack_h2((y0.x - mean) * rstd * ga0.x + be0.x,
                             (y0.y - mean) * rstd * ga0.y + be0.y);
            outv.y = pack_h2((y1.x - mean) * rstd * ga0.z + be0.z,
                             (y1.y - mean) * rstd * ga0.w + be0.w);
            outv.z = pack_h2((y2.x - mean) * rstd * ga1.x + be1.x,
                             (y2.y - mean) * rstd * ga1.y + be1.y);
            outv.w = pack_h2((y3.x - mean) * rstd * ga1.z + be1.z,
                             (y3.y - mean) * rstd * ga1.w + be1.w);
            *(uint4*)(smc + buf * STAGE_B + row * WRB + cc * 16) = outv;
        }
    };

    const uint32_t lrow = (uint32_t)(lane & 15);
    const uint32_t lhalf = (uint32_t)((lane >> 4) << 4);

    stage_A(0, 0);
    stage_A(1, 32);
    load_B(0, 0); cpa_commit();
    load_B(1, 32); cpa_commit();

#pragma unroll 1
    for (int it = 0; it < 32; ++it) {
        if (it < 31) cpa_wait<1>(); else cpa_wait<0>();
        __syncthreads();
        if (it + 2 < 32) {
            load_B((it + 2) % 3, (it + 2) * 32);
            cpa_commit();
            stage_A((it + 2) % 3, (it + 2) * 32);
        }

        const uint32_t baseA = smb + (uint32_t)((it % 3) * STAGE_B);
        const uint32_t baseB = baseA + PART_B;
        MMA_STAGE_BODY(baseA, baseB);
    }

#pragma unroll
    for (int mi = 0; mi < 4; mi++) {
        int r0 = bm + wm * 64 + mi * 16 + (lane >> 2);
#pragma unroll
        for (int ni = 0; ni < 4; ni++) {
            int col = bn + wn * 32 + ni * 8 + 2 * (lane & 3);
            float2 v01 = make_float2(c[mi][ni][0], c[mi][ni][1]);
            float2 v23 = make_float2(c[mi][ni][2], c[mi][ni][3]);
            *(float2*)(C + (size_t)r0 * DD + col) = v01;
            *(float2*)(C + (size_t)(r0 + 8) * DD + col) = v23;
        }
    }
}

// ---------------------------------------------------------------------------
// WKV segmented scan — exact reference recurrence with exp(0)-elimination
// ---------------------------------------------------------------------------
__global__ void wkv_p1(const float* __restrict__ td) {
    int gid = blockIdx.x * blockDim.x + threadIdx.x;
    if (gid >= NSEG * NC) return;
    int c = gid % DD;
    int r = gid / DD;
    int b = r % BB;
    int seg = r / BB;
    float w = -__expf(td[c]);
    const __half* kp = g_ko + ((size_t)b * SS + (size_t)seg * SEGL) * DD + c;
    float bb = -1e38f;
#pragma unroll 4
    for (int t = 0; t < SEGL; t++) {
        float kt = __half2float(kp[(size_t)t * DD]);
        float ww = bb + w;
        float d = ww - kt;
        float em = __expf(-fabsf(d));
        float p2 = fmaxf(ww, kt);
        bb = p2 + __logf(1.f + em + 1e-8f);
    }
    g_bs[seg * NC + b * DD + c] = bb;
}

// p2: serial combine across segments with chunked prefetch (MLP=8)
__global__ void wkv_p2(const float* __restrict__ td) {
    int ch = blockIdx.x * blockDim.x + threadIdx.x;
    if (ch >= NC) return;
    int c = ch % DD;
    float w = -__expf(td[c]);
    float Lw = (float)SEGL * w;
    float bin = -1e38f;
#pragma unroll 1
    for (int s0 = 0; s0 < NSEG; s0 += 8) {
        float bsv[8];
#pragma unroll
        for (int j = 0; j < 8; j++) bsv[j] = g_bs[(s0 + j) * NC + ch];
#pragma unroll
        for (int j = 0; j < 8; j++) {
            g_bin[(s0 + j) * NC + ch] = bin;
            float x = bin + Lw;
            float y = bsv[j];
            float em = __expf(-fabsf(x - y));
            bin = fmaxf(x, y) + __logf(1.f + em);
        }
    }
}

__global__ void wkv_p3(const float* __restrict__ td) {
    int gid = blockIdx.x * blockDim.x + threadIdx.x;
    if (gid >= NSEG * NC) return;
    int c = gid % DD;
    int r = gid / DD;
    int b = r % BB;
    int seg = r / BB;
    float w = -__expf(td[c]);
    const __half* kp = g_ko + ((size_t)b * SS + (size_t)seg * SEGL) * DD + c;
    const __half* vp = g_vo + ((size_t)b * SS + (size_t)seg * SEGL) * DD + c;
    int sidx = seg * NC + b * DD + c;
    float bb = g_bin[sidx];
    float aa = 0.f, lP = 0.f;
#pragma unroll 4
    for (int t = 0; t < SEGL; t++) {
        float kt = __half2float(kp[(size_t)t * DD]);
        float vt = __half2float(vp[(size_t)t * DD]);
        float ww = bb + w;
        float d = ww - kt;
        lP += fminf(d, 0.f);
        float em = __expf(-fabsf(d));
        float e1b = (d >= 0.f) ? 1.f : em;
        float e2b = (d >= 0.f) ? em : 1.f;
        aa = e1b * aa + e2b * vt;
        bb = fmaxf(ww, kt) + __logf(1.f + em + 1e-8f);
    }
    g_Cc[sidx] = aa;
    g_lP[sidx] = lP;
}

// p4: serial combine with chunked prefetch (MLP=8 on both arrays)
__global__ void wkv_p4() {
    int ch = blockIdx.x * blockDim.x + threadIdx.x;
    if (ch >= NC) return;
    float ain = 0.f;
#pragma unroll 1
    for (int s0 = 0; s0 < NSEG; s0 += 8) {
        float lpv[8], ccv[8];
#pragma unroll
        for (int j = 0; j < 8; j++) {
            lpv[j] = g_lP[(s0 + j) * NC + ch];
            ccv[j] = g_Cc[(s0 + j) * NC + ch];
        }
#pragma unroll
        for (int j = 0; j < 8; j++) {
            g_ain[(s0 + j) * NC + ch] = ain;
            ain = __expf(lpv[j]) * ain + ccv[j];
        }
    }
}

// Replay + sigmoid gate + fp16 y + GroupNorm partials (warp-shuffle)
__global__ void wkv_p5(const float* __restrict__ td, const float* __restrict__ tf) {
    int gid = blockIdx.x * blockDim.x + threadIdx.x;
    if (gid >= NSEG * NC) return;
    int c = gid % DD;
    int r = gid / DD;
    int b = r % BB;
    int seg = r / BB;
    float w = -__expf(td[c]);
    float u = tf[c];
    size_t off0 = ((size_t)b * SS + (size_t)seg * SEGL) * DD + c;
    const __half* kp = g_ko + off0;
    const __half* vp = g_vo + off0;
    const __half* rp = g_ro + off0;
    __half* yp = g_y + off0;
    int sidx = seg * NC + b * DD + c;
    float aa = g_ain[sidx];
    float bb = g_bin[sidx];
    float sum = 0.f, sq = 0.f;
#pragma unroll 2
    for (int t = 0; t < SEGL; t++) {
        float kt = __half2float(kp[(size_t)t * DD]);
        float vt = __half2float(vp[(size_t)t * DD]);
        float rv = __half2float(rp[(size_t)t * DD]);

        float wk = kt + u;
        float d1 = bb - wk;
        float em1 = __expf(-fabsf(d1));
        float e1 = (d1 >= 0.f) ? 1.f : em1;
        float e2 = (d1 >= 0.f) ? em1 : 1.f;
        float num = e1 * aa + e2 * vt;
        float den = 1.f + em1 + 1e-8f;
        float sg = 1.f + __expf(-rv);
        float y = num * __fdividef(1.f, den * sg);
        yp[(size_t)t * DD] = __float2half_rn(y);
        sum += y;
        sq += y * y;

        float ww = bb + w;
        float d = ww - kt;
        float em = __expf(-fabsf(d));
        float e1b = (d >= 0.f) ? 1.f : em;
        float e2b = (d >= 0.f) ? em : 1.f;
        aa = e1b * aa + e2b * vt;
        bb = fmaxf(ww, kt) + __logf(1.f + em + 1e-8f);
    }

#pragma unroll
    for (int o = 16; o > 0; o >>= 1) {
        sum += __shfl_down_sync(0xFFFFFFFFu, sum, o);
        sq += __shfl_down_sync(0xFFFFFFFFu, sq, o);
    }
    if ((threadIdx.x & 31) == 0) {
        int h = c >> 6;
        int half = (c >> 5) & 1;
        int pidx = (((seg * BB + b) * HH) + h) * 2 + half;
        g_psum[pidx] = sum;
        g_psq[pidx] = sq;
    }
}

// ---------------------------------------------------------------------------
// GroupNorm stats
// ---------------------------------------------------------------------------
__global__ void gn_mid() {
    int g = threadIdx.x;
    if (g >= BB * HH) return;
    int b = g / HH, h = g % HH;
    float s = 0.f, q = 0.f;
#pragma unroll
    for (int seg = 0; seg < NSEG; seg++) {
        int base = (((seg * BB + b) * HH) + h) * 2;
        s += g_psum[base] + g_psum[base + 1];
        q += g_psq[base] + g_psq[base + 1];
    }
    const float inv = 1.f / (float)(SS * HD);
    float mean = s * inv;
    float var = q * inv - mean * mean;
    g_mean[g] = mean;
    g_rstd[g] = rsqrtf(var + 1e-5f);
}

// ---------------------------------------------------------------------------
// Launch
// ---------------------------------------------------------------------------
extern "C" void kernel_launch(void* const* d_in, const int* in_sizes, int n_in,
                              void* d_out, int out_size) {
    const float* x     = (const float*)d_in[0];
    const float* tmr   = (const float*)d_in[1];
    const float* tmk   = (const float*)d_in[2];
    const float* tmv   = (const float*)d_in[3];
    const float* Wr    = (const float*)d_in[4];
    const float* Wk    = (const float*)d_in[5];
    const float* Wv    = (const float*)d_in[6];
    const float* Wo    = (const float*)d_in[7];
    const float* td    = (const float*)d_in[8];
    const float* tf    = (const float*)d_in[9];
    const float* gamma = (const float*)d_in[10];
    const float* beta  = (const float*)d_in[11];
    float* out = (float*)d_out;

    __half *ko, *ro, *vo, *yv, *hxr, *hxk, *hxv, *hwr, *hwk, *hwv, *hwo;
    cudaGetSymbolAddress((void**)&ko, g_ko);
    cudaGetSymbolAddress((void**)&ro, g_ro);
    cudaGetSymbolAddress((void**)&vo, g_vo);
    cudaGetSymbolAddress((void**)&yv, g_y);
    cudaGetSymbolAddress((void**)&hxr, g_hxr);
    cudaGetSymbolAddress((void**)&hxk, g_hxk);
    cudaGetSymbolAddress((void**)&hxv, g_hxv);
    cudaGetSymbolAddress((void**)&hwr, g_hWr);
    cudaGetSymbolAddress((void**)&hwk, g_hWk);
    cudaGetSymbolAddress((void**)&hwv, g_hWv);
    cudaGetSymbolAddress((void**)&hwo, g_hWo);

    cudaFuncSetAttribute(gemm_rkv,
                         cudaFuncAttributeMaxDynamicSharedMemorySize, GSM_BYTES);
    cudaFuncSetAttribute(gemm_wo,
                         cudaFuncAttributeMaxDynamicSharedMemorySize, GSM_BYTES);

    // 1. weights -> fp16 + token-shift mixing -> fp16
    const int WB4 = (DD * DD + 255) / 256;
    prep_w4<<<WB4, 256>>>(Wr, Wk, Wv, Wo, hwr, hwk, hwv, hwo);
    mix_kernel<<<(ELEMS / 4 + 255) / 256, 256>>>(x, tmr, tmk, tmv);

    // 2. r/k/v projections -> fp16
    dim3 gg3(DD / 128, MTOT / 128, 3);
    gemm_rkv<<<gg3, 256, GSM_BYTES>>>(hxr, hwr, ro,
                                      hxk, hwk, ko,
                                      hxv, hwv, vo);

    // 3. segmented WKV scan (NSEG=64) + gate + GN partials in p5
    wkv_p1<<<(NSEG * NC + 255) / 256, 256>>>(td);
    wkv_p2<<<(NC + 255) / 256, 256>>>(td);
    wkv_p3<<<(NSEG * NC + 255) / 256, 256>>>(td);
    wkv_p4<<<(NC + 255) / 256, 256>>>();
    wkv_p5<<<(NSEG * NC + 255) / 256, 256>>>(td, tf);

    // 4. GroupNorm stats
    gn_mid<<<1, 64>>>();

    // 5. output projection with fused GroupNorm on A
    dim3 gg1(DD / 128, MTOT / 128);
    gemm_wo<<<gg1, 256, GSM_BYTES>>>(yv, hwo, out, gamma, beta);
}

// round 15
// speedup vs baseline: 1.1181x; 1.0082x over previous
#include <cuda_runtime.h>
#include <cuda_fp16.h>
#include <math.h>
#include <cstdint>

// Problem constants
#define BB 4
#define SS 2048
#define DD 1024
#define HH 16
#define HD 64
#define MTOT (BB * SS)          // 8192
#define ELEMS (BB * SS * DD)    // 8,388,608
#define KDIM 1024

#define NSEG 64
#define SEGL (SS / NSEG)        // 32
#define NC (BB * DD)            // 4096

// ---------------------------------------------------------------------------
// Scratch (allocation-free: __device__ globals)
// ---------------------------------------------------------------------------
__device__ __half g_ko[ELEMS];         // k projection (fp16)
__device__ __half g_ro[ELEMS];         // r projection (fp16)
__device__ __half g_vo[ELEMS];         // v projection (fp16)
__device__ __half g_y[ELEMS];          // gated y = sigmoid(r)*wkv (fp16)

// fp16 activations (mix outputs)
__device__ __half g_hxr[ELEMS];
__device__ __half g_hxk[ELEMS];
__device__ __half g_hxv[ELEMS];

// fp16 weights
__device__ __half g_hWr[DD * DD];
__device__ __half g_hWk[DD * DD];
__device__ __half g_hWv[DD * DD];
__device__ __half g_hWo[DD * DD];

// mix-vector dedup flags (1 = differs from time_mix_r)
__device__ int g_flagk;
__device__ int g_flagv;

// WKV scan scratch
__device__ float g_bs[NSEG * NC];
__device__ float g_bin[NSEG * NC];
__device__ float g_Cc[NSEG * NC];
__device__ float g_lP[NSEG * NC];
__device__ float g_ain[NSEG * NC];

// GroupNorm scratch: partial per (seg, b, head, half-warp)
__device__ float g_psum[NSEG * BB * HH * 2];
__device__ float g_psq[NSEG * BB * HH * 2];
__device__ float g_mean[BB * HH];
__device__ float g_rstd[BB * HH];

// ---------------------------------------------------------------------------
// helpers
// ---------------------------------------------------------------------------
__device__ __forceinline__ uint32_t smem_u32(const void* p) {
    uint32_t a;
    asm("{ .reg .u64 t; cvta.to.shared.u64 t, %1; cvt.u32.u64 %0, t; }"
        : "=r"(a) : "l"(p));
    return a;
}

__device__ __forceinline__ void cpa16(uint32_t s, const void* g) {
    asm volatile("cp.async.cg.shared.global [%0], [%1], 16;\n" :: "r"(s), "l"(g));
}
__device__ __forceinline__ void cpa_commit() {
    asm volatile("cp.async.commit_group;\n" ::: "memory");
}
template <int N>
__device__ __forceinline__ void cpa_wait() {
    asm volatile("cp.async.wait_group %0;\n" :: "n"(N) : "memory");
}

__device__ __forceinline__ void ldsm4(uint32_t* r, uint32_t addr) {
    asm volatile(
        "ldmatrix.sync.aligned.m8n8.x4.shared.b16 {%0,%1,%2,%3}, [%4];"
        : "=r"(r[0]), "=r"(r[1]), "=r"(r[2]), "=r"(r[3]) : "r"(addr));
}

__device__ __forceinline__ void mma_f16(float* c, const uint32_t* a,
                                        uint32_t b0, uint32_t b1) {
    asm volatile(
        "mma.sync.aligned.m16n8k16.row.col.f32.f16.f16.f32 "
        "{%0,%1,%2,%3}, {%4,%5,%6,%7}, {%8,%9}, {%0,%1,%2,%3};\n"
        : "+f"(c[0]), "+f"(c[1]), "+f"(c[2]), "+f"(c[3])
        : "r"(a[0]), "r"(a[1]), "r"(a[2]), "r"(a[3]), "r"(b0), "r"(b1));
}

__device__ __forceinline__ uint32_t pack_h2(float a, float b) {
    __half2 h = __float22half2_rn(make_float2(a, b));
    return *(uint32_t*)&h;
}

// ---------------------------------------------------------------------------
// Kernel: check whether mix vectors differ from time_mix_r (1 block)
// ---------------------------------------------------------------------------
__global__ void chk_mix(const float* __restrict__ tmr,
                        const float* __restrict__ tmk,
                        const float* __restrict__ tmv) {
    __shared__ int fk, fv;
    if (threadIdx.x == 0) { fk = 0; fv = 0; }
    __syncthreads();
    for (int i = threadIdx.x; i < DD; i += blockDim.x) {
        float r = tmr[i];
        if (tmk[i] != r) atomicOr(&fk, 1);
        if (tmv[i] != r) atomicOr(&fv, 1);
    }
    __syncthreads();
    if (threadIdx.x == 0) { g_flagk = fk; g_flagv = fv; }
}

// ---------------------------------------------------------------------------
// Kernel: fused weight conversion + token-shift mixing.
// Index range [0, 4*N4): weights fp32->fp16. [4*N4, 4*N4+TOT4): mixing.
// Mix writes g_hxk/g_hxv only when the mix vectors differ from tmr.
// ---------------------------------------------------------------------------
__global__ void prep_mix(const float* __restrict__ W0, const float* __restrict__ W1,
                         const float* __restrict__ W2, const float* __restrict__ W3,
                         const float* __restrict__ x,
                         const float* __restrict__ tmr,
                         const float* __restrict__ tmk,
                         const float* __restrict__ tmv,
                         __half* __restrict__ H0, __half* __restrict__ H1,
                         __half* __restrict__ H2, __half* __restrict__ H3) {
    const int N4 = DD * DD / 4;
    const int TOT4 = ELEMS / 4;
    int idx = blockIdx.x * blockDim.x + threadIdx.x;
    if (idx < 4 * N4) {
        int m = idx / N4;
        int i = idx - m * N4;
        const float* W = (m == 0) ? W0 : (m == 1) ? W1 : (m == 2) ? W2 : W3;
        __half* H = (m == 0) ? H0 : (m == 1) ? H1 : (m == 2) ? H2 : H3;
        float4 a = ((const float4*)W)[i];
        uint2 h;
        h.x = pack_h2(a.x, a.y);
        h.y = pack_h2(a.z, a.w);
        ((uint2*)H)[i] = h;
        return;
    }
    idx -= 4 * N4;
    if (idx >= TOT4) return;

    const int D4 = DD / 4;
    int d4 = idx % D4;
    int bs = idx / D4;
    int s = bs % SS;

    const float4* x4 = (const float4*)x;
    float4 xv_ = x4[idx];
    float4 sh = (s > 0) ? x4[idx - D4] : make_float4(0.f, 0.f, 0.f, 0.f);
    float4 mr = ((const float4*)tmr)[d4];

    uint2 h;
    h.x = pack_h2(xv_.x * mr.x + sh.x * (1.f - mr.x),
                  xv_.y * mr.y + sh.y * (1.f - mr.y));
    h.y = pack_h2(xv_.z * mr.z + sh.z * (1.f - mr.z),
                  xv_.w * mr.w + sh.w * (1.f - mr.w));
    ((uint2*)g_hxr)[idx] = h;

    if (g_flagk) {
        float4 mk = ((const float4*)tmk)[d4];
        h.x = pack_h2(xv_.x * mk.x + sh.x * (1.f - mk.x),
                      xv_.y * mk.y + sh.y * (1.f - mk.y));
        h.y = pack_h2(xv_.z * mk.z + sh.z * (1.f - mk.z),
                      xv_.w * mk.w + sh.w * (1.f - mk.w));
        ((uint2*)g_hxk)[idx] = h;
    }
    if (g_flagv) {
        float4 mv = ((const float4*)tmv)[d4];
        h.x = pack_h2(xv_.x * mv.x + sh.x * (1.f - mv.x),
                      xv_.y * mv.y + sh.y * (1.f - mv.y));
        h.y = pack_h2(xv_.z * mv.z + sh.z * (1.f - mv.z),
                      xv_.w * mv.w + sh.w * (1.f - mv.w));
        ((uint2*)g_hxv)[idx] = h;
    }
}

// ---------------------------------------------------------------------------
// Shared GEMM geometry + validated simple MMA body
// ---------------------------------------------------------------------------
#define WRB 80
#define PART_B (128 * WRB)
#define STAGE_B (2 * PART_B)
#define GSM_BYTES (3 * STAGE_B)

#define MMA_STAGE_BODY(baseA, baseB)                                          \
    do {                                                                      \
        _Pragma("unroll")                                                     \
        for (int ks = 0; ks < 2; ks++) {                                      \
            const uint32_t koff = (uint32_t)(ks * 32) + lhalf;                \
            uint32_t bf[2][4];                                                \
            _Pragma("unroll")                                                 \
            for (int np = 0; np < 2; np++) {                                  \
                uint32_t row = (uint32_t)(wn * 32 + np * 16) + lrow;          \
                ldsm4(bf[np], (baseB) + row * WRB + koff);                    \
            }                                                                 \
            _Pragma("unroll")                                                 \
            for (int mi = 0; mi < 4; mi++) {                                  \
                uint32_t arow = (uint32_t)(wm * 64 + mi * 16) + lrow;         \
                uint32_t ah[4];                                               \
                ldsm4(ah, (baseA) + arow * WRB + koff);                       \
                _Pragma("unroll")                                             \
                for (int ni = 0; ni < 4; ni++) {                              \
                    int np = ni >> 1, sel = ni & 1;                           \
                    mma_f16(c[mi][ni], ah, bf[np][sel], bf[np][sel + 2]);     \
                }                                                             \
            }                                                                 \
        }                                                                     \
    } while (0)

// ---------------------------------------------------------------------------
// r/k/v GEMM: fp16 in, fp16 out; A pointer selected via mix-dedup flags
// ---------------------------------------------------------------------------
__global__ __launch_bounds__(256, 2)
void gemm_rkv(const __half* __restrict__ A0, const __half* __restrict__ B0,
              __half* __restrict__ C0,
              const __half* __restrict__ A1, const __half* __restrict__ B1,
              __half* __restrict__ C1,
              const __half* __restrict__ A2, const __half* __restrict__ B2,
              __half* __restrict__ C2) {
    extern __shared__ char smc[];
    const uint32_t smb = smem_u32(smc);
    const int z = blockIdx.z;
    const __half* A = (z == 0) ? A0 : (z == 1) ? (g_flagk ? A1 : A0)
                                               : (g_flagv ? A2 : A0);
    const __half* Bm = (z == 0) ? B0 : (z == 1) ? B1 : B2;
    __half* C = (z == 0) ? C0 : (z == 1) ? C1 : C2;

    const int tid = threadIdx.x;
    const int lane = tid & 31;
    const int wid = tid >> 5;
    const int wm = wid >> 2;
    const int wn = wid & 3;
    const int bm = blockIdx.y * 128;
    const int bn = blockIdx.x * 128;

    const __half* srcA = A + (size_t)bm * KDIM;
    const __half* srcB = Bm + (size_t)bn * KDIM;

    float c[4][4][4];
#pragma unroll
    for (int i = 0; i < 4; i++)
#pragma unroll
        for (int j = 0; j < 4; j++)
#pragma unroll
            for (int q = 0; q < 4; q++) c[i][j][q] = 0.f;

    auto load_stage = [&](int buf, int k0) {
#pragma unroll
        for (int i = 0; i < 4; i++) {
            int id = tid + i * 256;
            int part = id >> 9;
            int pid = id & 511;
            int row = pid >> 2;
            int cc = pid & 3;
            uint32_t saddr = smb + (uint32_t)(buf * STAGE_B + part * PART_B +
                                              row * WRB + cc * 16);
            const __half* g = (part == 0 ? srcA : srcB) + (size_t)row * KDIM +
                              k0 + cc * 8;
            cpa16(saddr, g);
        }
    };

    const uint32_t lrow = (uint32_t)(lane & 15);
    const uint32_t lhalf = (uint32_t)((lane >> 4) << 4);

    load_stage(0, 0); cpa_commit();
    load_stage(1, 32); cpa_commit();

#pragma unroll 1
    for (int it = 0; it < 32; ++it) {
        if (it < 31) cpa_wait<1>(); else cpa_wait<0>();
        __syncthreads();
        if (it + 2 < 32) {
            load_stage((it + 2) % 3, (it + 2) * 32);
            cpa_commit();
        }

        const uint32_t baseA = smb + (uint32_t)((it % 3) * STAGE_B);
        const uint32_t baseB = baseA + PART_B;
        MMA_STAGE_BODY(baseA, baseB);
    }

#pragma unroll
    for (int mi = 0; mi < 4; mi++) {
        int r0 = bm + wm * 64 + mi * 16 + (lane >> 2);
#pragma unroll
        for (int ni = 0; ni < 4; ni++) {
            int col = bn + wn * 32 + ni * 8 + 2 * (lane & 3);
            __half2 h01 = __float22half2_rn(make_float2(c[mi][ni][0], c[mi][ni][1]));
            __half2 h23 = __float22half2_rn(make_float2(c[mi][ni][2], c[mi][ni][3]));
            *(__half2*)(C + (size_t)r0 * DD + col) = h01;
            *(__half2*)(C + (size_t)(r0 + 8) * DD + col) = h23;
        }
    }
}

// ---------------------------------------------------------------------------
// Wo GEMM with fused GroupNorm on the A operand (validated)
// ---------------------------------------------------------------------------
__global__ __launch_bounds__(256, 2)
void gemm_wo(const __half* __restrict__ Y, const __half* __restrict__ Bw,
             float* __restrict__ C,
             const float* __restrict__ gamma, const float* __restrict__ beta) {
    extern __shared__ char smc[];
    const uint32_t smb = smem_u32(smc);

    const int tid = threadIdx.x;
    const int lane = tid & 31;
    const int wid = tid >> 5;
    const int wm = wid >> 2;
    const int wn = wid & 3;
    const int bm = blockIdx.y * 128;
    const int bn = blockIdx.x * 128;

    const __half* srcB = Bw + (size_t)bn * KDIM;

    const int arow0 = (tid + 0) >> 2, acc0 = (tid + 0) & 3;
    const int arow1 = (tid + 256) >> 2, acc1 = (tid + 256) & 3;

    float c[4][4][4];
#pragma unroll
    for (int i = 0; i < 4; i++)
#pragma unroll
        for (int j = 0; j < 4; j++)
#pragma unroll
            for (int q = 0; q < 4; q++) c[i][j][q] = 0.f;

    auto load_B = [&](int buf, int k0) {
#pragma unroll
        for (int i = 0; i < 2; i++) {
            int id = tid + i * 256;
            int row = id >> 2;
            int cc = id & 3;
            uint32_t saddr = smb + (uint32_t)(buf * STAGE_B + PART_B +
                                              row * WRB + cc * 16);
            cpa16(saddr, srcB + (size_t)row * KDIM + k0 + cc * 8);
        }
    };

    auto stage_A = [&](int buf, int k0) {
#pragma unroll
        for (int i = 0; i < 2; i++) {
            int row = (i == 0) ? arow0 : arow1;
            int cc = (i == 0) ? acc0 : acc1;
            int c0 = k0 + cc * 8;
            int m = bm + row;
            uint4 raw = *(const uint4*)(Y + (size_t)m * KDIM + c0);
            int grp = (m >> 11) * HH + (c0 >> 6);
            float mean = __ldg(g_mean + grp);
            float rstd = __ldg(g_rstd + grp);
            float4 ga0 = *(const float4*)(gamma + c0);
            float4 ga1 = *(const float4*)(gamma + c0 + 4);
            float4 be0 = *(const float4*)(beta + c0);
            float4 be1 = *(const float4*)(beta + c0 + 4);
            float2 y0 = __half22float2(*(__half2*)&raw.x);
            float2 y1 = __half22float2(*(__half2*)&raw.y);
            float2 y2 = __half22float2(*(__half2*)&raw.z);
            float2 y3 = __half22float2(*(__half2*)&raw.w);
            uint4 outv;
            outv.x = pack_h2((y0.x - mean) * rstd * ga0.x + be0.x,
                             (y0.y - mean) * rstd * ga0.y + be0.y);
            outv.y = pack_h2((y1.x - mean) * rstd * ga0.z + be0.z,
                             (y1.y - mean) * rstd * ga0.w + be0.w);
            outv.z = pack_h2((y2.x - mean) * rstd * ga1.x + be1.x,
                             (y2.y - mean) * rstd * ga1.y + be1.y);
            outv.w = pack_h2((y3.x - mean) * rstd * ga1.z + be1.z,
                             (y3.y - mean) * rstd * ga1.w + be1.w);
            *(uint4*)(smc + buf * STAGE_B + row * WRB + cc * 16) = outv;
        }
    };

    const uint32_t lrow = (uint32_t)(lane & 15);
    const uint32_t lhalf = (uint32_t)((lane >> 4) << 4);

    stage_A(0, 0);
    stage_A(1, 32);
    load_B(0, 0); cpa_commit();
    load_B(1, 32); cpa_commit();

#pragma unroll 1
    for (int it = 0; it < 32; ++it) {
        if (it < 31) cpa_wait<1>(); else cpa_wait<0>();
        __syncthreads();
        if (it + 2 < 32) {
            load_B((it + 2) % 3, (it + 2) * 32);
            cpa_commit();
            stage_A((it + 2) % 3, (it + 2) * 32);
        }

        const uint32_t baseA = smb + (uint32_t)((it % 3) * STAGE_B);
        const uint32_t baseB = baseA + PART_B;
        MMA_STAGE_BODY(baseA, baseB);
    }

#pragma unroll
    for (int mi = 0; mi < 4; mi++) {
        int r0 = bm + wm * 64 + mi * 16 + (lane >> 2);
#pragma unroll
        for (int ni = 0; ni < 4; ni++) {
            int col = bn + wn * 32 + ni * 8 + 2 * (lane & 3);
            float2 v01 = make_float2(c[mi][ni][0], c[mi][ni][1]);
            float2 v23 = make_float2(c[mi][ni][2], c[mi][ni][3]);
            *(float2*)(C + (size_t)r0 * DD + col) = v01;
            *(float2*)(C + (size_t)(r0 + 8) * DD + col) = v23;
        }
    }
}

// ---------------------------------------------------------------------------
// WKV segmented scan
// p1: segment b-summary in LINEAR space w/ max normalization — 1 exp, 0 log
//     per step (log once at end). Mathematically identical to the LSE chain.
// ---------------------------------------------------------------------------
__global__ void wkv_p1(const float* __restrict__ td) {
    int gid = blockIdx.x * blockDim.x + threadIdx.x;
    if (gid >= NSEG * NC) return;
    int c = gid % DD;
    int r = gid / DD;
    int b = r % BB;
    int seg = r / BB;
    float w = -__expf(td[c]);
    const __half* kp = g_ko + ((size_t)b * SS + (size_t)seg * SEGL) * DD + c;
    float M = -1e38f, nD = 0.f;
#pragma unroll 4
    for (int t = 0; t < SEGL; t++) {
        float kt = __half2float(kp[(size_t)t * DD]);
        float Mw = M + w;
        float d = Mw - kt;
        float em = __expf(-fabsf(d));
        if (d >= 0.f) {
            M = Mw;
            nD = nD + em;
        } else {
            M = kt;
            nD = nD * em + 1.f;
        }
    }
    g_bs[seg * NC + b * DD + c] = M + __logf(nD + 1e-8f);
}

// p2: serial combine across segments with chunked prefetch (MLP=8)
__global__ void wkv_p2(const float* __restrict__ td) {
    int ch = blockIdx.x * blockDim.x + threadIdx.x;
    if (ch >= NC) return;
    int c = ch % DD;
    float w = -__expf(td[c]);
    float Lw = (float)SEGL * w;
    float bin = -1e38f;
#pragma unroll 1
    for (int s0 = 0; s0 < NSEG; s0 += 8) {
        float bsv[8];
#pragma unroll
        for (int j = 0; j < 8; j++) bsv[j] = g_bs[(s0 + j) * NC + ch];
#pragma unroll
        for (int j = 0; j < 8; j++) {
            g_bin[(s0 + j) * NC + ch] = bin;
            float x = bin + Lw;
            float y = bsv[j];
            float em = __expf(-fabsf(x - y));
            bin = fmaxf(x, y) + __logf(1.f + em);
        }
    }
}

__global__ void wkv_p3(const float* __restrict__ td) {
    int gid = blockIdx.x * blockDim.x + threadIdx.x;
    if (gid >= NSEG * NC) return;
    int c = gid % DD;
    int r = gid / DD;
    int b = r % BB;
    int seg = r / BB;
    float w = -__expf(td[c]);
    const __half* kp = g_ko + ((size_t)b * SS + (size_t)seg * SEGL) * DD + c;
    const __half* vp = g_vo + ((size_t)b * SS + (size_t)seg * SEGL) * DD + c;
    int sidx = seg * NC + b * DD + c;
    float bb = g_bin[sidx];
    float aa = 0.f, lP = 0.f;
#pragma unroll 4
    for (int t = 0; t < SEGL; t++) {
        float kt = __half2float(kp[(size_t)t * DD]);
        float vt = __half2float(vp[(size_t)t * DD]);
        float ww = bb + w;
        float d = ww - kt;
        lP += fminf(d, 0.f);
        float em = __expf(-fabsf(d));
        float e1b = (d >= 0.f) ? 1.f : em;
        float e2b = (d >= 0.f) ? em : 1.f;
        aa = e1b * aa + e2b * vt;
        bb = fmaxf(ww, kt) + __logf(1.f + em + 1e-8f);
    }
    g_Cc[sidx] = aa;
    g_lP[sidx] = lP;
}

// p4: serial combine with chunked prefetch (MLP=8 on both arrays)
__global__ void wkv_p4() {
    int ch = blockIdx.x * blockDim.x + threadIdx.x;
    if (ch >= NC) return;
    float ain = 0.f;
#pragma unroll 1
    for (int s0 = 0; s0 < NSEG; s0 += 8) {
        float lpv[8], ccv[8];
#pragma unroll
        for (int j = 0; j < 8; j++) {
            lpv[j] = g_lP[(s0 + j) * NC + ch];
            ccv[j] = g_Cc[(s0 + j) * NC + ch];
        }
#pragma unroll
        for (int j = 0; j < 8; j++) {
            g_ain[(s0 + j) * NC + ch] = ain;
            ain = __expf(lpv[j]) * ain + ccv[j];
        }
    }
}

// Replay + sigmoid gate + fp16 y + GroupNorm partials (warp-shuffle)
__global__ void wkv_p5(const float* __restrict__ td, const float* __restrict__ tf) {
    int gid = blockIdx.x * blockDim.x + threadIdx.x;
    if (gid >= NSEG * NC) return;
    int c = gid % DD;
    int r = gid / DD;
    int b = r % BB;
    int seg = r / BB;
    float w = -__expf(td[c]);
    float u = tf[c];
    size_t off0 = ((size_t)b * SS + (size_t)seg * SEGL) * DD + c;
    const __half* kp = g_ko + off0;
    const __half* vp = g_vo + off0;
    const __half* rp = g_ro + off0;
    __half* yp = g_y + off0;
    int sidx = seg * NC + b * DD + c;
    float aa = g_ain[sidx];
    float bb = g_bin[sidx];
    float sum = 0.f, sq = 0.f;
#pragma unroll 2
    for (int t = 0; t < SEGL; t++) {
        float kt = __half2float(kp[(size_t)t * DD]);
        float vt = __half2float(vp[(size_t)t * DD]);
        float rv = __half2float(rp[(size_t)t * DD]);

        float wk = kt + u;
        float d1 = bb - wk;
        float em1 = __expf(-fabsf(d1));
        float e1 = (d1 >= 0.f) ? 1.f : em1;
        float e2 = (d1 >= 0.f) ? em1 : 1.f;
        float num = e1 * aa + e2 * vt;
        float den = 1.f + em1 + 1e-8f;
        float sg = 1.f + __expf(-rv);
        float y = num * __fdividef(1.f, den * sg);
        yp[(size_t)t * DD] = __float2half_rn(y);
        sum += y;
        sq += y * y;

        float ww = bb + w;
        float d = ww - kt;
        float em = __expf(-fabsf(d));
        float e1b = (d >= 0.f) ? 1.f : em;
        float e2b = (d >= 0.f) ? em : 1.f;
        aa = e1b * aa + e2b * vt;
        bb = fmaxf(ww, kt) + __logf(1.f + em + 1e-8f);
    }

#pragma unroll
    for (int o = 16; o > 0; o >>= 1) {
        sum += __shfl_down_sync(0xFFFFFFFFu, sum, o);
        sq += __shfl_down_sync(0xFFFFFFFFu, sq, o);
    }
    if ((threadIdx.x & 31) == 0) {
        int h = c >> 6;
        int half = (c >> 5) & 1;
        int pidx = (((seg * BB + b) * HH) + h) * 2 + half;
        g_psum[pidx] = sum;
        g_psq[pidx] = sq;
    }
}

// ---------------------------------------------------------------------------
// GroupNorm stats
// ---------------------------------------------------------------------------
__global__ void gn_mid() {
    int g = threadIdx.x;
    if (g >= BB * HH) return;
    int b = g / HH, h = g % HH;
    float s = 0.f, q = 0.f;
#pragma unroll
    for (int seg = 0; seg < NSEG; seg++) {
        int base = (((seg * BB + b) * HH) + h) * 2;
        s += g_psum[base] + g_psum[base + 1];
        q += g_psq[base] + g_psq[base + 1];
    }
    const float inv = 1.f / (float)(SS * HD);
    float mean = s * inv;
    float var = q * inv - mean * mean;
    g_mean[g] = mean;
    g_rstd[g] = rsqrtf(var + 1e-5f);
}

// ---------------------------------------------------------------------------
// Launch
// ---------------------------------------------------------------------------
extern "C" void kernel_launch(void* const* d_in, const int* in_sizes, int n_in,
                              void* d_out, int out_size) {
    const float* x     = (const float*)d_in[0];
    const float* tmr   = (const float*)d_in[1];
    const float* tmk   = (const float*)d_in[2];
    const float* tmv   = (const float*)d_in[3];
    const float* Wr    = (const float*)d_in[4];
    const float* Wk    = (const float*)d_in[5];
    const float* Wv    = (const float*)d_in[6];
    const float* Wo    = (const float*)d_in[7];
    const float* td    = (const float*)d_in[8];
    const float* tf    = (const float*)d_in[9];
    const float* gamma = (const float*)d_in[10];
    const float* beta  = (const float*)d_in[11];
    float* out = (float*)d_out;

    __half *ko, *ro, *vo, *yv, *hxr, *hxk, *hxv, *hwr, *hwk, *hwv, *hwo;
    cudaGetSymbolAddress((void**)&ko, g_ko);
    cudaGetSymbolAddress((void**)&ro, g_ro);
    cudaGetSymbolAddress((void**)&vo, g_vo);
    cudaGetSymbolAddress((void**)&yv, g_y);
    cudaGetSymbolAddress((void**)&hxr, g_hxr);
    cudaGetSymbolAddress((void**)&hxk, g_hxk);
    cudaGetSymbolAddress((void**)&hxv, g_hxv);
    cudaGetSymbolAddress((void**)&hwr, g_hWr);
    cudaGetSymbolAddress((void**)&hwk, g_hWk);
    cudaGetSymbolAddress((void**)&hwv, g_hWv);
    cudaGetSymbolAddress((void**)&hwo, g_hWo);

    cudaFuncSetAttribute(gemm_rkv,
                         cudaFuncAttributeMaxDynamicSharedMemorySize, GSM_BYTES);
    cudaFuncSetAttribute(gemm_wo,
                         cudaFuncAttributeMaxDynamicSharedMemorySize, GSM_BYTES);

    // 1. mix-dedup flags, then fused weight-convert + token-shift mixing
    chk_mix<<<1, 256>>>(tmr, tmk, tmv);
    const int PTOT = 4 * (DD * DD / 4) + ELEMS / 4;
    prep_mix<<<(PTOT + 255) / 256, 256>>>(Wr, Wk, Wv, Wo, x, tmr, tmk, tmv,
                                          hwr, hwk, hwv, hwo);

    // 2. r/k/v projections -> fp16 (A selected by flags inside kernel)
    dim3 gg3(DD / 128, MTOT / 128, 3);
    gemm_rkv<<<gg3, 256, GSM_BYTES>>>(hxr, hwr, ro,
                                      hxk, hwk, ko,
                                      hxv, hwv, vo);

    // 3. segmented WKV scan (NSEG=64) + gate + GN partials in p5
    wkv_p1<<<(NSEG * NC + 255) / 256, 256>>>(td);
    wkv_p2<<<(NC + 255) / 256, 256>>>(td);
    wkv_p3<<<(NSEG * NC + 255) / 256, 256>>>(td);
    wkv_p4<<<(NC + 255) / 256, 256>>>();
    wkv_p5<<<(NSEG * NC + 255) / 256, 256>>>(td, tf);

    // 4. GroupNorm stats
    gn_mid<<<1, 64>>>();

    // 5. output projection with fused GroupNorm on A
    dim3 gg1(DD / 128, MTOT / 128);
    gemm_wo<<<gg1, 256, GSM_BYTES>>>(yv, hwo, out, gamma, beta);
}